// round 14
// baseline (speedup 1.0000x reference)
#include <cuda_runtime.h>
#include <cstdint>

#define NV      400000
#define CIN     64
#define COUT    64
#define KT      27
#define TILE_M  128
#define THREADS 128

#define FS_PAD 68      // Fs row stride (words)
#define FS_WORDS (TILE_M * FS_PAD)           // 8704
#define BUF_WORDS FS_WORDS
#define SMEM_BYTES (2 * BUF_WORDS * 4)       // 69632 -> 3 CTAs/SM

// ---------------- device global: fragment-major tf32 weights ----------------
// layout: [k][ks][h][lane][nt]  (27*8*2*32*8 = 110592 words)
__device__ float g_wf[KT * CIN * COUT];

__device__ __forceinline__ uint32_t cvt_tf32(float x) {
    uint32_t u;
    asm("cvt.rna.tf32.f32 %0, %1;" : "=r"(u) : "f"(x));
    return u;
}
__device__ __forceinline__ uint32_t smem_u32(const void* p) {
    uint32_t a;
    asm("{ .reg .u64 t; cvta.to.shared.u64 t, %1; cvt.u32.u64 %0, t; }" : "=r"(a) : "l"(p));
    return a;
}
__device__ __forceinline__ void cp_async16(uint32_t dst, const void* src, uint32_t src_bytes) {
    asm volatile("cp.async.cg.shared.global [%0], [%1], 16, %2;"
                 :: "r"(dst), "l"(src), "r"(src_bytes) : "memory");
}
__device__ __forceinline__ void cp_commit() {
    asm volatile("cp.async.commit_group;" ::: "memory");
}
template <int N>
__device__ __forceinline__ void cp_wait() {
    asm volatile("cp.async.wait_group %0;" :: "n"(N) : "memory");
}
__device__ __forceinline__ void mma_tf32(float* d, const uint32_t* a, uint32_t b0, uint32_t b1) {
    asm volatile(
        "mma.sync.aligned.m16n8k8.row.col.f32.tf32.tf32.f32 "
        "{%0,%1,%2,%3}, {%4,%5,%6,%7}, {%8,%9}, {%0,%1,%2,%3};"
        : "+f"(d[0]), "+f"(d[1]), "+f"(d[2]), "+f"(d[3])
        : "r"(a[0]), "r"(a[1]), "r"(a[2]), "r"(a[3]), "r"(b0), "r"(b1));
}

// ---------------- prep: repack weights fragment-major, tf32 ----------------
// dst[((k*8+ks)*2+h)*256 + lane*8 + nt] = tf32( w[k][ks*8 + lr + h*4][nt*8 + lq] )
__global__ void prep_w(const float* __restrict__ w) {
    int e = blockIdx.x * 256 + threadIdx.x;              // 0..110591
    const int nt   = e & 7;
    const int lane = (e >> 3) & 31;
    const int h    = (e >> 8) & 1;
    const int ks   = (e >> 9) & 7;
    const int k    = e >> 12;
    const int lq = lane >> 2;
    const int lr = lane & 3;
    const float v = w[k * 4096 + (ks * 8 + lr + h * 4) * 64 + nt * 8 + lq];
    g_wf[e] = __uint_as_float(cvt_tf32(v));
}

// ---------------- main kernel ----------------
// CTA: 128 threads = 4 warps, tile M=128 x N=64; warp tile 32x64 (mt=2, nt=8).
// A double-buffered in smem via cp.async; B fragments streamed from L2 with
// register prefetch one k-step ahead (no W smem). 68KB smem -> 3 CTAs/SM.
__global__ __launch_bounds__(THREADS, 3)
void spconv_pipe(const float* __restrict__ feats,
                 const float* __restrict__ bias,
                 const int*   __restrict__ nbr,
                 float*       __restrict__ out)
{
    extern __shared__ uint32_t smem[];
    const uint32_t smem_base = smem_u32(smem);

    const int tid  = threadIdx.x;
    const int warp = tid >> 5;
    const int lane = tid & 31;
    const int lq   = lane >> 2;
    const int lr   = lane & 3;
    const int vb   = warp * 32;
    const int jbase = blockIdx.x * TILE_M;    // NV % TILE_M == 0

    // gather geometry: 16 lanes per row
    const int f4   = tid & 15;
    const int rowg = tid >> 4;

    // per-thread B-fragment pointer for (k, ks): 4 x uint4
    const uint4* wf_base = reinterpret_cast<const uint4*>(g_wf) + lane * 2;

    // accumulators seeded with bias
    float acc[2][8][4];
    #pragma unroll
    for (int nt = 0; nt < 8; ++nt) {
        const float bx = __ldg(bias + nt * 8 + lr * 2);
        const float by = __ldg(bias + nt * 8 + lr * 2 + 1);
        #pragma unroll
        for (int mt = 0; mt < 2; ++mt) {
            acc[mt][nt][0] = bx; acc[mt][nt][1] = by;
            acc[mt][nt][2] = bx; acc[mt][nt][3] = by;
        }
    }

    // ---- idx prefetch ----
    int idxs[16];
    auto load_idxs = [&](int k) {
        const int* nk = nbr + (size_t)k * NV + jbase + rowg;
        #pragma unroll
        for (int it = 0; it < 16; ++it)
            idxs[it] = __ldg(nk + 8 * it);
    };

    // ---- staging: A gather only ----
    auto stage = [&](int buf) {
        const uint32_t fbase = smem_base + (buf * BUF_WORDS) * 4;
        #pragma unroll
        for (int it = 0; it < 16; ++it) {
            const int v   = rowg + 8 * it;
            const int idx = idxs[it];
            const float* src = feats + (size_t)(idx < 0 ? 0 : idx) * CIN + f4 * 4;
            cp_async16(fbase + (v * FS_PAD + f4 * 4) * 4, src, idx >= 0 ? 16u : 0u);
        }
    };

    // B fragment loader: (k, ks) -> 4 x LDG.128 (coalesced, L2-hot)
    auto load_b = [&](int k, int ks, uint4* bq) {
        const uint4* p = wf_base + (size_t)(k * 8 + ks) * 128;  // 512 words = 128 uint4 per (k,ks)
        bq[0] = __ldg(p);        // h=0, nt 0..3
        bq[1] = __ldg(p + 1);    // h=0, nt 4..7
        bq[2] = __ldg(p + 64);   // h=1, nt 0..3
        bq[3] = __ldg(p + 65);   // h=1, nt 4..7
    };

    // prologue
    load_idxs(0);
    stage(0);
    cp_commit();
    load_idxs(1);

    for (int k = 0; k < KT; ++k) {
        const int cb = k & 1;
        __syncthreads();                 // done reading buffer cb (tap k-2)

        if (k + 1 < KT) {
            stage(cb ^ 1);
            cp_commit();
            if (k + 2 < KT) load_idxs(k + 2);
            cp_wait<1>();
        } else {
            cp_wait<0>();
        }
        __syncthreads();

        const uint32_t* Fs = smem + cb * BUF_WORDS;

        uint4 bq[2][4];
        load_b(k, 0, bq[0]);
        #pragma unroll
        for (int ks = 0; ks < 8; ++ks) {
            const int cur = ks & 1;                 // compile-time (full unroll)
            if (ks < 7) load_b(k, ks + 1, bq[cur ^ 1]);
            const uint32_t* bw = reinterpret_cast<const uint32_t*>(bq[cur]);
            const int kb = ks * 8;
            #pragma unroll
            for (int mt = 0; mt < 2; ++mt) {
                uint32_t a[4];
                const int base = (vb + mt * 16 + lq) * FS_PAD + kb + lr;
                a[0] = cvt_tf32(__uint_as_float(Fs[base]));
                a[1] = cvt_tf32(__uint_as_float(Fs[base + 8 * FS_PAD]));
                a[2] = cvt_tf32(__uint_as_float(Fs[base + 4]));
                a[3] = cvt_tf32(__uint_as_float(Fs[base + 8 * FS_PAD + 4]));
                #pragma unroll
                for (int nt = 0; nt < 8; ++nt)
                    mma_tf32(acc[mt][nt], a, bw[nt], bw[8 + nt]);
            }
        }
    }

    // ---- epilogue: store float2 pairs (bias folded; no guards) ----
    #pragma unroll
    for (int mt = 0; mt < 2; ++mt) {
        const int r0 = jbase + vb + mt * 16 + lq;
        #pragma unroll
        for (int nt = 0; nt < 8; ++nt) {
            const int col = nt * 8 + lr * 2;
            float2 o0 = make_float2(acc[mt][nt][0], acc[mt][nt][1]);
            float2 o1 = make_float2(acc[mt][nt][2], acc[mt][nt][3]);
            *reinterpret_cast<float2*>(out + (size_t)r0 * COUT + col)       = o0;
            *reinterpret_cast<float2*>(out + (size_t)(r0 + 8) * COUT + col) = o1;
        }
    }
}

extern "C" void kernel_launch(void* const* d_in, const int* in_sizes, int n_in,
                              void* d_out, int out_size) {
    const float* feats  = (const float*)d_in[0];   // [N, 64] f32
    const float* weight = (const float*)d_in[1];   // [27, 64, 64] f32
    const float* bias   = (const float*)d_in[2];   // [64] f32
    const int*   nbr    = (const int*)  d_in[3];   // [27, N] i32
    float*       out    = (float*)d_out;           // [N, 64] f32

    static bool init_done = false;
    if (!init_done) {
        cudaFuncSetAttribute(spconv_pipe,
                             cudaFuncAttributeMaxDynamicSharedMemorySize, SMEM_BYTES);
        init_done = true;
    }
    prep_w<<<(KT * CIN * COUT) / 256, 256>>>(weight);
    spconv_pipe<<<NV / TILE_M, THREADS, SMEM_BYTES>>>(feats, bias, nbr, out);
}

// round 15
// speedup vs baseline: 1.0442x; 1.0442x over previous
#include <cuda_runtime.h>
#include <cstdint>

#define NV      400000
#define CIN     64
#define COUT    64
#define KT      27
#define TILE_M  128
#define THREADS 128

#define FS_PAD 68      // Fs row stride (words)
#define WS_PAD 72      // Ws row stride (words)
#define FS_WORDS (TILE_M * FS_PAD)   // 8704
#define WS_WORDS (CIN * WS_PAD)      // 4608
#define BUF_WORDS (FS_WORDS + WS_WORDS)      // 13312
#define SMEM_BYTES (2 * BUF_WORDS * 4)       // 106496 -> 2 CTAs/SM

// ---------------- device global: pre-converted tf32 weights ----------------
__device__ float g_w[KT * CIN * COUT];

__device__ __forceinline__ uint32_t cvt_tf32(float x) {
    uint32_t u;
    asm("cvt.rna.tf32.f32 %0, %1;" : "=r"(u) : "f"(x));
    return u;
}
__device__ __forceinline__ uint32_t smem_u32(const void* p) {
    uint32_t a;
    asm("{ .reg .u64 t; cvta.to.shared.u64 t, %1; cvt.u32.u64 %0, t; }" : "=r"(a) : "l"(p));
    return a;
}
__device__ __forceinline__ void cp_async16(uint32_t dst, const void* src, uint32_t src_bytes) {
    asm volatile("cp.async.cg.shared.global [%0], [%1], 16, %2;"
                 :: "r"(dst), "l"(src), "r"(src_bytes) : "memory");
}
__device__ __forceinline__ void cp_commit() {
    asm volatile("cp.async.commit_group;" ::: "memory");
}
template <int N>
__device__ __forceinline__ void cp_wait() {
    asm volatile("cp.async.wait_group %0;" :: "n"(N) : "memory");
}
__device__ __forceinline__ void mma_tf32(float* d, const uint32_t* a, const uint32_t* b) {
    asm volatile(
        "mma.sync.aligned.m16n8k8.row.col.f32.tf32.tf32.f32 "
        "{%0,%1,%2,%3}, {%4,%5,%6,%7}, {%8,%9}, {%0,%1,%2,%3};"
        : "+f"(d[0]), "+f"(d[1]), "+f"(d[2]), "+f"(d[3])
        : "r"(a[0]), "r"(a[1]), "r"(a[2]), "r"(a[3]), "r"(b[0]), "r"(b[1]));
}

// ---------------- prep kernel: weights -> tf32 ----------------
__global__ void prep_w(const float* __restrict__ w) {
    int i = blockIdx.x * 256 + threadIdx.x;              // KT*CIN*COUT
    g_w[i] = __uint_as_float(cvt_tf32(w[i]));
}

// ---------------- main kernel ----------------
// CTA: 128 threads = 4 warps, tile M=128 x N=64; warp tile 32x64 (mt=2, nt=8).
// Double-buffered cp.async; STAGING ISSUE IS FUSED INTO THE COMPUTE LOOP:
// during ks=0..3 of tap k we issue tap k+1's gather/W cp.asyncs into the
// other buffer, commit after the ks loop, and the single top-of-tap
// __syncthreads orders tap k-1's buffer reads before tap k+1's writes.
__global__ __launch_bounds__(THREADS, 2)
void spconv_pipe(const float* __restrict__ feats,
                 const float* __restrict__ bias,
                 const int*   __restrict__ nbr,
                 float*       __restrict__ out)
{
    extern __shared__ uint32_t smem[];
    const uint32_t smem_base = smem_u32(smem);

    const int tid  = threadIdx.x;
    const int warp = tid >> 5;
    const int lane = tid & 31;
    const int lq   = lane >> 2;
    const int lr   = lane & 3;
    const int vb   = warp * 32;
    const int jbase = blockIdx.x * TILE_M;    // NV % TILE_M == 0

    // gather geometry: 16 lanes per row
    const int f4   = tid & 15;
    const int rowg = tid >> 4;

    // accumulators seeded with bias
    float acc[2][8][4];
    #pragma unroll
    for (int nt = 0; nt < 8; ++nt) {
        const float bx = __ldg(bias + nt * 8 + lr * 2);
        const float by = __ldg(bias + nt * 8 + lr * 2 + 1);
        #pragma unroll
        for (int mt = 0; mt < 2; ++mt) {
            acc[mt][nt][0] = bx; acc[mt][nt][1] = by;
            acc[mt][nt][2] = bx; acc[mt][nt][3] = by;
        }
    }

    // ---- idx prefetch: 16 rows per lane-group ----
    int idxs[16];
    auto load_idxs = [&](int k) {
        const int* nk = nbr + (size_t)k * NV + jbase + rowg;
        #pragma unroll
        for (int it = 0; it < 16; ++it)
            idxs[it] = __ldg(nk + 8 * it);
    };

    // ---- prologue: full staging of tap 0 ----
    load_idxs(0);
    {
        const uint32_t fbase = smem_base;            // buffer 0
        const uint32_t wbase = fbase + FS_WORDS * 4;
        #pragma unroll
        for (int it = 0; it < 16; ++it) {
            const int v   = rowg + 8 * it;
            const int idx = idxs[it];
            const float* src = feats + (size_t)(idx < 0 ? 0 : idx) * CIN + f4 * 4;
            cp_async16(fbase + (v * FS_PAD + f4 * 4) * 4, src, idx >= 0 ? 16u : 0u);
        }
        const float* wsrc = g_w;
        #pragma unroll
        for (int r = 0; r < 8; ++r) {
            const int l = tid + r * THREADS;
            cp_async16(wbase + ((l >> 4) * WS_PAD + (l & 15) * 4) * 4,
                       wsrc + l * 4, 16u);
        }
    }
    cp_commit();
    load_idxs(1);    // for tap 1's staging (issued during tap 0 compute)

    for (int k = 0; k < KT; ++k) {
        const int cb = k & 1;
        cp_wait<0>();            // my buffer-cb group complete
        __syncthreads();         // cb visible to all; all done reading cb^1 (tap k-1)

        const uint32_t* Fs = smem + cb * BUF_WORDS;
        const uint32_t* Ws = Fs + FS_WORDS;

        const bool do_stage = (k + 1 < KT);
        const uint32_t fbase = smem_base + ((cb ^ 1) * BUF_WORDS) * 4;
        const uint32_t wbase = fbase + FS_WORDS * 4;
        const float* wsrc = g_w + (size_t)(k + 1) * (CIN * COUT);

        #pragma unroll
        for (int ks = 0; ks < 8; ++ks) {
            const int kb = ks * 8;
            uint32_t b[8][2];
            #pragma unroll
            for (int nt = 0; nt < 8; ++nt) {
                const int ncol = nt * 8 + lq;
                b[nt][0] = Ws[(kb + lr)     * WS_PAD + ncol];
                b[nt][1] = Ws[(kb + lr + 4) * WS_PAD + ncol];
            }

            // fused staging for tap k+1: 4 gathers + 2 W copies per ks (ks<4)
            if (do_stage && ks < 4) {
                #pragma unroll
                for (int t = 0; t < 4; ++t) {
                    const int it  = ks * 4 + t;
                    const int v   = rowg + 8 * it;
                    const int idx = idxs[it];
                    const float* src = feats + (size_t)(idx < 0 ? 0 : idx) * CIN + f4 * 4;
                    cp_async16(fbase + (v * FS_PAD + f4 * 4) * 4, src, idx >= 0 ? 16u : 0u);
                }
                #pragma unroll
                for (int t = 0; t < 2; ++t) {
                    const int l = tid + (ks * 2 + t) * THREADS;   // 0..1023
                    cp_async16(wbase + ((l >> 4) * WS_PAD + (l & 15) * 4) * 4,
                               wsrc + l * 4, 16u);
                }
            }

            #pragma unroll
            for (int mt = 0; mt < 2; ++mt) {
                uint32_t a[4];
                const int base = (vb + mt * 16 + lq) * FS_PAD + kb + lr;
                a[0] = cvt_tf32(__uint_as_float(Fs[base]));
                a[1] = cvt_tf32(__uint_as_float(Fs[base + 8 * FS_PAD]));
                a[2] = cvt_tf32(__uint_as_float(Fs[base + 4]));
                a[3] = cvt_tf32(__uint_as_float(Fs[base + 8 * FS_PAD + 4]));
                #pragma unroll
                for (int nt = 0; nt < 8; ++nt)
                    mma_tf32(acc[mt][nt], a, b[nt]);
            }
        }

        if (do_stage) cp_commit();
        if (k + 2 < KT) load_idxs(k + 2);   // consumed during tap k+1's compute
    }

    // ---- epilogue: store float2 pairs (bias folded; no guards) ----
    #pragma unroll
    for (int mt = 0; mt < 2; ++mt) {
        const int r0 = jbase + vb + mt * 16 + lq;
        #pragma unroll
        for (int nt = 0; nt < 8; ++nt) {
            const int col = nt * 8 + lr * 2;
            float2 o0 = make_float2(acc[mt][nt][0], acc[mt][nt][1]);
            float2 o1 = make_float2(acc[mt][nt][2], acc[mt][nt][3]);
            *reinterpret_cast<float2*>(out + (size_t)r0 * COUT + col)       = o0;
            *reinterpret_cast<float2*>(out + (size_t)(r0 + 8) * COUT + col) = o1;
        }
    }
}

extern "C" void kernel_launch(void* const* d_in, const int* in_sizes, int n_in,
                              void* d_out, int out_size) {
    const float* feats  = (const float*)d_in[0];   // [N, 64] f32
    const float* weight = (const float*)d_in[1];   // [27, 64, 64] f32
    const float* bias   = (const float*)d_in[2];   // [64] f32
    const int*   nbr    = (const int*)  d_in[3];   // [27, N] i32
    float*       out    = (float*)d_out;           // [N, 64] f32

    static bool init_done = false;
    if (!init_done) {
        cudaFuncSetAttribute(spconv_pipe,
                             cudaFuncAttributeMaxDynamicSharedMemorySize, SMEM_BYTES);
        init_done = true;
    }
    prep_w<<<(KT * CIN * COUT) / 256, 256>>>(weight);
    spconv_pipe<<<NV / TILE_M, THREADS, SMEM_BYTES>>>(feats, bias, nbr, out);
}

// round 16
// speedup vs baseline: 1.1877x; 1.1375x over previous
#include <cuda_runtime.h>
#include <cstdint>

#define NV      400000
#define CIN     64
#define COUT    64
#define KT      27
#define TILE_M  128
#define THREADS 128
#define NSTAGE  (KT * 2)          // 54 half-tap stages

#define FA_PAD  36                // A-half row stride (words): bank stride 4
#define A_WORDS (TILE_M * FA_PAD) // 4608
#define WS_PAD  72                // W row stride (words): bank stride 8
#define W_WORDS (32 * WS_PAD)     // 2304
#define BUF_WORDS (A_WORDS + W_WORDS)    // 6912
#define SMEM_BYTES (2 * BUF_WORDS * 4)   // 55296 -> 4 CTAs/SM

// ---------------- device global: pre-converted tf32 weights ----------------
__device__ float g_w[KT * CIN * COUT];

__device__ __forceinline__ uint32_t cvt_tf32(float x) {
    uint32_t u;
    asm("cvt.rna.tf32.f32 %0, %1;" : "=r"(u) : "f"(x));
    return u;
}
__device__ __forceinline__ uint32_t smem_u32(const void* p) {
    uint32_t a;
    asm("{ .reg .u64 t; cvta.to.shared.u64 t, %1; cvt.u32.u64 %0, t; }" : "=r"(a) : "l"(p));
    return a;
}
__device__ __forceinline__ void cp_async16(uint32_t dst, const void* src, uint32_t src_bytes) {
    asm volatile("cp.async.cg.shared.global [%0], [%1], 16, %2;"
                 :: "r"(dst), "l"(src), "r"(src_bytes) : "memory");
}
__device__ __forceinline__ void cp_commit() {
    asm volatile("cp.async.commit_group;" ::: "memory");
}
template <int N>
__device__ __forceinline__ void cp_wait() {
    asm volatile("cp.async.wait_group %0;" :: "n"(N) : "memory");
}
__device__ __forceinline__ void mma_tf32(float* d, const uint32_t* a, const uint32_t* b) {
    asm volatile(
        "mma.sync.aligned.m16n8k8.row.col.f32.tf32.tf32.f32 "
        "{%0,%1,%2,%3}, {%4,%5,%6,%7}, {%8,%9}, {%0,%1,%2,%3};"
        : "+f"(d[0]), "+f"(d[1]), "+f"(d[2]), "+f"(d[3])
        : "r"(a[0]), "r"(a[1]), "r"(a[2]), "r"(a[3]), "r"(b[0]), "r"(b[1]));
}

// ---------------- prep kernel: weights -> tf32 ----------------
__global__ void prep_w(const float* __restrict__ w) {
    int i = blockIdx.x * 256 + threadIdx.x;              // KT*CIN*COUT
    g_w[i] = __uint_as_float(cvt_tf32(w[i]));
}

// ---------------- main kernel ----------------
// CTA: 128 threads = 4 warps, tile M=128 x N=64; warp tile 32x64 (mt=2,nt=8).
// Pipeline granularity = HALF-TAP (k, khalf): A-half (128x32) + W-half (32x64)
// double-buffered in 55KB smem -> 4 CTAs/SM (16 warps) for phase interleave.
// acc accumulates across both halves (serial K-split; no reduction needed).
__global__ __launch_bounds__(THREADS, 4)
void spconv_pipe(const float* __restrict__ feats,
                 const float* __restrict__ bias,
                 const int*   __restrict__ nbr,
                 float*       __restrict__ out)
{
    extern __shared__ uint32_t smem[];
    const uint32_t smem_base = smem_u32(smem);

    const int tid  = threadIdx.x;
    const int warp = tid >> 5;
    const int lane = tid & 31;
    const int lq   = lane >> 2;
    const int lr   = lane & 3;
    const int vb   = warp * 32;
    const int jbase = blockIdx.x * TILE_M;    // NV % TILE_M == 0

    // gather geometry: 8 lanes per half-row (128B), 16 row-groups
    const int f8    = tid & 7;                // 16B chunk within half-row
    const int rowg  = tid >> 3;               // row group 0..15

    // accumulators seeded with bias
    float acc[2][8][4];
    #pragma unroll
    for (int nt = 0; nt < 8; ++nt) {
        const float bx = __ldg(bias + nt * 8 + lr * 2);
        const float by = __ldg(bias + nt * 8 + lr * 2 + 1);
        #pragma unroll
        for (int mt = 0; mt < 2; ++mt) {
            acc[mt][nt][0] = bx; acc[mt][nt][1] = by;
            acc[mt][nt][2] = bx; acc[mt][nt][3] = by;
        }
    }

    // ---- idx prefetch: 8 rows per lane-group (shared by both halves of a tap) ----
    int idxs[8];
    auto load_idxs = [&](int t) {
        const int* nk = nbr + (size_t)t * NV + jbase + rowg;
        #pragma unroll
        for (int it = 0; it < 8; ++it)
            idxs[it] = __ldg(nk + 16 * it);
    };

    // ---- staging: stage s = (tap k = s>>1, half h = s&1) ----
    auto stage = [&](int s, int buf) {
        const int k = s >> 1;
        const int h = s & 1;
        const uint32_t fbase = smem_base + (buf * BUF_WORDS) * 4;
        const uint32_t wbase = fbase + A_WORDS * 4;
        #pragma unroll
        for (int it = 0; it < 8; ++it) {
            const int row = rowg + 16 * it;
            const int idx = idxs[it];
            const float* src = feats + (size_t)(idx < 0 ? 0 : idx) * CIN + h * 32 + f8 * 4;
            cp_async16(fbase + (row * FA_PAD + f8 * 4) * 4, src, idx >= 0 ? 16u : 0u);
        }
        const float* wsrc = g_w + (size_t)k * (CIN * COUT) + h * 2048;
        #pragma unroll
        for (int r = 0; r < 4; ++r) {
            const int l = tid + r * THREADS;   // 0..511
            cp_async16(wbase + ((l >> 4) * WS_PAD + (l & 15) * 4) * 4,
                       wsrc + l * 4, 16u);
        }
    };

    // prologue: stage 0 into buffer 0
    load_idxs(0);
    stage(0, 0);
    cp_commit();

    for (int s = 0; s < NSTAGE; ++s) {
        const int cb = s & 1;
        __syncthreads();                 // all warps done reading buffer cb (stage s-2)

        if (s + 1 < NSTAGE) {
            stage(s + 1, cb ^ 1);        // idxs currently hold tap (s+1)>>1
            cp_commit();
            // next iteration stages s+2; if it starts a new tap, load its idxs now
            if (((s + 2) & 1) == 0 && (s + 2) < NSTAGE)
                load_idxs((s + 2) >> 1);
            cp_wait<1>();                // buffer cb (staged last iteration) ready
        } else {
            cp_wait<0>();
        }
        __syncthreads();

        const uint32_t* Fs = smem + cb * BUF_WORDS;
        const uint32_t* Ws = Fs + A_WORDS;
        #pragma unroll
        for (int ks = 0; ks < 4; ++ks) {
            const int kb = ks * 8;
            uint32_t b[8][2];
            #pragma unroll
            for (int nt = 0; nt < 8; ++nt) {
                const int ncol = nt * 8 + lq;
                b[nt][0] = Ws[(kb + lr)     * WS_PAD + ncol];
                b[nt][1] = Ws[(kb + lr + 4) * WS_PAD + ncol];
            }
            #pragma unroll
            for (int mt = 0; mt < 2; ++mt) {
                uint32_t a[4];
                const int base = (vb + mt * 16 + lq) * FA_PAD + kb + lr;
                a[0] = cvt_tf32(__uint_as_float(Fs[base]));
                a[1] = cvt_tf32(__uint_as_float(Fs[base + 8 * FA_PAD]));
                a[2] = cvt_tf32(__uint_as_float(Fs[base + 4]));
                a[3] = cvt_tf32(__uint_as_float(Fs[base + 8 * FA_PAD + 4]));
                #pragma unroll
                for (int nt = 0; nt < 8; ++nt)
                    mma_tf32(acc[mt][nt], a, b[nt]);
            }
        }
    }

    // ---- epilogue: store float2 pairs (bias folded; no guards) ----
    #pragma unroll
    for (int mt = 0; mt < 2; ++mt) {
        const int r0 = jbase + vb + mt * 16 + lq;
        #pragma unroll
        for (int nt = 0; nt < 8; ++nt) {
            const int col = nt * 8 + lr * 2;
            float2 o0 = make_float2(acc[mt][nt][0], acc[mt][nt][1]);
            float2 o1 = make_float2(acc[mt][nt][2], acc[mt][nt][3]);
            *reinterpret_cast<float2*>(out + (size_t)r0 * COUT + col)       = o0;
            *reinterpret_cast<float2*>(out + (size_t)(r0 + 8) * COUT + col) = o1;
        }
    }
}

extern "C" void kernel_launch(void* const* d_in, const int* in_sizes, int n_in,
                              void* d_out, int out_size) {
    const float* feats  = (const float*)d_in[0];   // [N, 64] f32
    const float* weight = (const float*)d_in[1];   // [27, 64, 64] f32
    const float* bias   = (const float*)d_in[2];   // [64] f32
    const int*   nbr    = (const int*)  d_in[3];   // [27, N] i32
    float*       out    = (float*)d_out;           // [N, 64] f32

    static bool init_done = false;
    if (!init_done) {
        cudaFuncSetAttribute(spconv_pipe,
                             cudaFuncAttributeMaxDynamicSharedMemorySize, SMEM_BYTES);
        init_done = true;
    }
    prep_w<<<(KT * CIN * COUT) / 256, 256>>>(weight);
    spconv_pipe<<<NV / TILE_M, THREADS, SMEM_BYTES>>>(feats, bias, nbr, out);
}